// round 1
// baseline (speedup 1.0000x reference)
#include <cuda_runtime.h>

// Problem constants
#define BATCH 16
#define CH    8
#define HH    512
#define WW    512
#define HW    262144          // H*W
#define NPIX  4194304         // B*H*W

// Scratch (device globals — no allocation allowed in kernel_launch)
__device__ float g_q[NPIX];                 // [B,H,W]
__device__ float g_k[NPIX];                 // [B,H,W]
__device__ float g_v[BATCH * CH * HW];      // [B,C,H,W]
__device__ float g_attn[BATCH * HH * HH];   // [B,H,H]

// ---------------------------------------------------------------------------
// Kernel 1: fused q/k/v 1x1 convs.  One thread per pixel (b,h,w).
// ---------------------------------------------------------------------------
__global__ void qkv_kernel(const float* __restrict__ x,
                           const float* __restrict__ Wq, const float* __restrict__ bq,
                           const float* __restrict__ Wk, const float* __restrict__ bk,
                           const float* __restrict__ Wv, const float* __restrict__ bv)
{
    __shared__ float sWq[8], sWk[8], sWv[64], sBv[8], sB[2];
    const int tid = threadIdx.x;
    if (tid < 8)  { sWq[tid] = Wq[tid]; sWk[tid] = Wk[tid]; sBv[tid] = bv[tid]; }
    if (tid >= 8 && tid < 72) sWv[tid - 8] = Wv[tid - 8];
    if (tid == 72) sB[0] = bq[0];
    if (tid == 73) sB[1] = bk[0];
    __syncthreads();

    const long p  = (long)blockIdx.x * 256 + tid;          // 0 .. NPIX
    const int  b  = (int)(p >> 18);
    const int  hw = (int)(p & (HW - 1));
    const float* xp = x + (long)b * CH * HW + hw;

    float xv[8];
#pragma unroll
    for (int c = 0; c < 8; c++) xv[c] = xp[(long)c * HW];

    float q = sB[0], k = sB[1];
#pragma unroll
    for (int c = 0; c < 8; c++) { q += xv[c] * sWq[c]; k += xv[c] * sWk[c]; }
    g_q[p] = q;
    g_k[p] = k;

    float* vp = g_v + (long)b * CH * HW + hw;
#pragma unroll
    for (int o = 0; o < 8; o++) {
        float v = sBv[o];
#pragma unroll
        for (int c = 0; c < 8; c++) v += xv[c] * sWv[o * 8 + c];
        vp[(long)o * HW] = v;
    }
}

// ---------------------------------------------------------------------------
// SGEMM 512x512x512, 128x128 CTA tile, 8x8 per-thread microtile, BK=8.
//   BNT=true : C[i][j] = sum_k A[i][k] * B[j][k]   (B stored [N][K]) -> q k^T
//   BNT=false: C[i][j] = sum_k A[i][k] * B[k][j]   (B stored [K][N]) -> attn v
// A advances per-z by (z >> aShift)*262144; B and C by z*262144.
// ---------------------------------------------------------------------------
template <bool BNT>
__global__ void __launch_bounds__(256, 2)
sgemm512(const float* __restrict__ Aall, const float* __restrict__ Ball,
         float* __restrict__ Call, int aShift)
{
    const int z = blockIdx.z;
    const float* A = Aall + (long)(z >> aShift) * 262144;
    const float* B = Ball + (long)z * 262144;
    float*       C = Call + (long)z * 262144;

    const int m0 = blockIdx.y * 128;
    const int n0 = blockIdx.x * 128;

    __shared__ float As[8][128];
    __shared__ float Bs[8][128];

    const int t  = threadIdx.x;
    const int ar = t >> 1, ac = (t & 1) * 4;   // A (and NT-B) loaders: row, k-seg
    const int br = t >> 5, bc = (t & 31) * 4;  // NN-B loader: k-row, n-col
    const int ty = t >> 4, tx = t & 15;        // 16x16 thread grid -> 8x8 tiles

    float acc[8][8] = {};

    for (int k0 = 0; k0 < 512; k0 += 8) {
        const float4 av = *(const float4*)(A + (long)(m0 + ar) * 512 + k0 + ac);
        float4 bv;
        if (BNT) bv = *(const float4*)(B + (long)(n0 + ar) * 512 + k0 + ac);
        else     bv = *(const float4*)(B + (long)(k0 + br) * 512 + n0 + bc);

        __syncthreads();
        As[ac + 0][ar] = av.x; As[ac + 1][ar] = av.y;
        As[ac + 2][ar] = av.z; As[ac + 3][ar] = av.w;
        if (BNT) {
            Bs[ac + 0][ar] = bv.x; Bs[ac + 1][ar] = bv.y;
            Bs[ac + 2][ar] = bv.z; Bs[ac + 3][ar] = bv.w;
        } else {
            *(float4*)(&Bs[br][bc]) = bv;
        }
        __syncthreads();

#pragma unroll
        for (int kk = 0; kk < 8; kk++) {
            float a[8], b[8];
            *(float4*)(a)     = *(const float4*)(&As[kk][ty * 8]);
            *(float4*)(a + 4) = *(const float4*)(&As[kk][ty * 8 + 4]);
            *(float4*)(b)     = *(const float4*)(&Bs[kk][tx * 8]);
            *(float4*)(b + 4) = *(const float4*)(&Bs[kk][tx * 8 + 4]);
#pragma unroll
            for (int r = 0; r < 8; r++)
#pragma unroll
                for (int s = 0; s < 8; s++)
                    acc[r][s] += a[r] * b[s];
        }
    }

#pragma unroll
    for (int r = 0; r < 8; r++) {
        float* cp = C + (long)(m0 + ty * 8 + r) * 512 + n0 + tx * 8;
        *(float4*)(cp)     = make_float4(acc[r][0], acc[r][1], acc[r][2], acc[r][3]);
        *(float4*)(cp + 4) = make_float4(acc[r][4], acc[r][5], acc[r][6], acc[r][7]);
    }
}

// ---------------------------------------------------------------------------
// Row softmax over g_attn: 8192 rows of 512, one CTA (128 threads) per row.
// ---------------------------------------------------------------------------
__global__ void softmax_kernel()
{
    const int row = blockIdx.x;
    const int tid = threadIdx.x;
    float* rp = g_attn + (long)row * 512;

    float4 v = *(float4*)(rp + tid * 4);

    float m = fmaxf(fmaxf(v.x, v.y), fmaxf(v.z, v.w));
#pragma unroll
    for (int o = 16; o > 0; o >>= 1) m = fmaxf(m, __shfl_xor_sync(0xFFFFFFFFu, m, o));

    __shared__ float sred[4];
    const int wid = tid >> 5, lane = tid & 31;
    if (lane == 0) sred[wid] = m;
    __syncthreads();
    m = fmaxf(fmaxf(sred[0], sred[1]), fmaxf(sred[2], sred[3]));
    __syncthreads();

    v.x = __expf(v.x - m); v.y = __expf(v.y - m);
    v.z = __expf(v.z - m); v.w = __expf(v.w - m);

    float s = v.x + v.y + v.z + v.w;
#pragma unroll
    for (int o = 16; o > 0; o >>= 1) s += __shfl_xor_sync(0xFFFFFFFFu, s, o);
    if (lane == 0) sred[wid] = s;
    __syncthreads();
    s = sred[0] + sred[1] + sred[2] + sred[3];

    const float inv = 1.0f / s;
    v.x *= inv; v.y *= inv; v.z *= inv; v.w *= inv;
    *(float4*)(rp + tid * 4) = v;
}

// ---------------------------------------------------------------------------
// Launch
// ---------------------------------------------------------------------------
extern "C" void kernel_launch(void* const* d_in, const int* in_sizes, int n_in,
                              void* d_out, int out_size)
{
    const float* x  = (const float*)d_in[0];
    const float* Wq = (const float*)d_in[1];
    const float* bq = (const float*)d_in[2];
    const float* Wk = (const float*)d_in[3];
    const float* bk = (const float*)d_in[4];
    const float* Wv = (const float*)d_in[5];
    const float* bv = (const float*)d_in[6];
    float* out = (float*)d_out;

    // Resolve device-global scratch addresses (host cannot use symbols directly)
    float *pq, *pk, *pv, *pattn;
    cudaGetSymbolAddress((void**)&pq,    g_q);
    cudaGetSymbolAddress((void**)&pk,    g_k);
    cudaGetSymbolAddress((void**)&pv,    g_v);
    cudaGetSymbolAddress((void**)&pattn, g_attn);

    // 1) q,k,v
    qkv_kernel<<<NPIX / 256, 256>>>(x, Wq, bq, Wk, bk, Wv, bv);

    // 2) S = q k^T per batch   (z = b, A stride z, B stride z)
    sgemm512<true><<<dim3(4, 4, BATCH), 256>>>(pq, pk, pattn, 0);

    // 3) softmax rows
    softmax_kernel<<<BATCH * HH, 128>>>();

    // 4) out = attn @ v per (b,c)   (z = b*8+c, A uses z>>3)
    sgemm512<false><<<dim3(4, 4, BATCH * CH), 256>>>(pattn, pv, out, 3);
}

// round 3
// speedup vs baseline: 2.5510x; 2.5510x over previous
#include <cuda_runtime.h>
#include <cstdint>

#define BATCH 16
#define HW    262144
#define NPIX  4194304

// ---------------- scratch (device globals; no runtime allocation) ----------
__device__ float g_qhi[NPIX], g_qlo[NPIX], g_khi[NPIX], g_klo[NPIX];   // [B,H,W]
__device__ float g_vT[BATCH * 8 * HW];                                 // [B,C,W,H]
__device__ float g_attn[BATCH * HW];                                   // [B,H,H]

// ---------------- helpers ---------------------------------------------------
__device__ __forceinline__ float tf32r(float x) {
    uint32_t u; asm("cvt.rna.tf32.f32 %0, %1;" : "=r"(u) : "f"(x));
    return __uint_as_float(u);
}
#define CPA16(s, g)   asm volatile("cp.async.cg.shared.global [%0], [%1], 16;" :: "r"(s), "l"(g) : "memory")
#define CPA_COMMIT()  asm volatile("cp.async.commit_group;" ::: "memory")
#define CPA_WAIT(n)   asm volatile("cp.async.wait_group %0;" :: "n"(n) : "memory")

__device__ __forceinline__ uint32_t smem_u32(const void* p) {
    uint32_t a;
    asm("{ .reg .u64 t; cvta.to.shared.u64 t, %1; cvt.u32.u64 %0, t; }" : "=r"(a) : "l"(p));
    return a;
}
// byte offset of element (row, col-float) in a [rows][32]-float K-major tile,
// XOR-swizzled so mma fragment reads are bank-conflict-free.
__device__ __forceinline__ uint32_t swz(int r, int c) {
    uint32_t o = (uint32_t)(r * 128 + c * 4);
    return o ^ ((o >> 3) & 0x70);
}
__device__ __forceinline__ uint32_t lds32(uint32_t a) {
    uint32_t v; asm volatile("ld.shared.b32 %0, [%1];" : "=r"(v) : "r"(a));
    return v;
}
#define MMA_TF32(c, a, b0, b1) \
    asm volatile("mma.sync.aligned.m16n8k8.row.col.f32.tf32.tf32.f32 " \
                 "{%0,%1,%2,%3},{%4,%5,%6,%7},{%8,%9},{%0,%1,%2,%3};" \
                 : "+f"((c)[0]), "+f"((c)[1]), "+f"((c)[2]), "+f"((c)[3]) \
                 : "r"((a)[0]), "r"((a)[1]), "r"((a)[2]), "r"((a)[3]), "r"(b0), "r"(b1))

// ---------------------------------------------------------------------------
// Fused q/k/v 1x1 convs.  q,k written as tf32 hi/lo pairs (3xTF32 logits),
// v transposed to [B,C,W,H] (tf32-rounded) via SMEM tile transpose.
// ---------------------------------------------------------------------------
__global__ void __launch_bounds__(256)
qkv_kernel(const float* __restrict__ x,
           const float* __restrict__ Wq, const float* __restrict__ bq,
           const float* __restrict__ Wk, const float* __restrict__ bk,
           const float* __restrict__ Wv, const float* __restrict__ bv)
{
    __shared__ float sWq[8], sWk[8], sWv[64], sBv[8], sB2[2];
    __shared__ float sv[8][32][33];
    const int tid = threadIdx.x;
    if (tid < 8) { sWq[tid] = Wq[tid]; sWk[tid] = Wk[tid]; sBv[tid] = bv[tid]; }
    if (tid >= 8 && tid < 72) sWv[tid - 8] = Wv[tid - 8];
    if (tid == 72) sB2[0] = bq[0];
    if (tid == 73) sB2[1] = bk[0];
    __syncthreads();

    const int b = blockIdx.z, h0 = blockIdx.y * 32, w0 = blockIdx.x * 32;
    const int j = tid & 31, i0 = tid >> 5;

    for (int ii = 0; ii < 4; ii++) {
        const int i = i0 + ii * 8;
        const int h = h0 + i, w = w0 + j;
        const size_t pb = ((size_t)b * 8) * HW + (size_t)h * 512 + w;
        float xv[8];
#pragma unroll
        for (int c = 0; c < 8; c++) xv[c] = x[pb + (size_t)c * HW];

        float q = sB2[0], k = sB2[1];
#pragma unroll
        for (int c = 0; c < 8; c++) { q += xv[c] * sWq[c]; k += xv[c] * sWk[c]; }
        const size_t p = (size_t)b * HW + (size_t)h * 512 + w;
        const float qh = tf32r(q), kh = tf32r(k);
        g_qhi[p] = qh; g_qlo[p] = tf32r(q - qh);
        g_khi[p] = kh; g_klo[p] = tf32r(k - kh);

#pragma unroll
        for (int o = 0; o < 8; o++) {
            float v = sBv[o];
#pragma unroll
            for (int c = 0; c < 8; c++) v += xv[c] * sWv[o * 8 + c];
            sv[o][i][j] = tf32r(v);
        }
    }
    __syncthreads();

    for (int ii = 0; ii < 4; ii++) {
        const int wl = i0 + ii * 8;   // local w
        const int hl = j;             // local h
#pragma unroll
        for (int c = 0; c < 8; c++) {
            g_vT[(((size_t)b * 8 + c) * 512 + (w0 + wl)) * 512 + (h0 + hl)] = sv[c][hl][wl];
        }
    }
}

// ---------------------------------------------------------------------------
// mma.sync tf32 GEMM: C[m,n] = sum_k A[m,k]*B[n,k], per-z 512x512x512.
// CTA 128x128, 8 warps (4x2), warp tile 32x64, K-chunk 32, 3-stage cp.async.
// SPLIT: 3xTF32 using (Ahi,Alo,Bhi,Blo).
// ---------------------------------------------------------------------------
template <bool SPLIT>
__global__ void __launch_bounds__(256)
gemm_mma(const float* __restrict__ Ahi, const float* __restrict__ Alo,
         const float* __restrict__ Bhi, const float* __restrict__ Blo,
         float* __restrict__ Cb, int aShift)
{
    constexpr int STAGES = 3;
    constexpr uint32_t TILE = 128 * 32 * 4;                   // 16 KB
    constexpr uint32_t SB   = SPLIT ? 4 * TILE : 2 * TILE;    // stage bytes

    extern __shared__ char smem[];
    const uint32_t s0 = smem_u32(smem);

    const int tid  = threadIdx.x;
    const int lane = tid & 31;
    const int wid  = tid >> 5;
    const int wm   = (wid & 3) * 32;      // warp m offset
    const int wn   = (wid >> 2) * 64;     // warp n offset
    const int gid  = lane >> 2;           // fragment group id (0..7)
    const int tig  = lane & 3;            // thread in group  (0..3)

    const int z = blockIdx.z;
    const size_t m0 = (size_t)blockIdx.y * 128;
    const size_t n0 = (size_t)blockIdx.x * 128;
    const float* Ah = Ahi + (size_t)(z >> aShift) * HW;
    const float* Al = Alo + (size_t)(z >> aShift) * HW;
    const float* Bh = Bhi + (size_t)z * HW;
    const float* Bl = Blo + (size_t)z * HW;
    float* C = Cb + (size_t)z * HW;

    // loader mapping: 256 threads -> (seg 0..7) x (row0 0..31), 4 rows each
    const int seg  = tid & 7;
    const int row0 = tid >> 3;
    const uint32_t soff = swz(0, seg * 4);   // swizzle of (0, seg*4..) base; rows add r*128 then re-xor
    (void)soff;

    auto load_chunk = [&](int c) {
        const uint32_t base = s0 + (uint32_t)(c % STAGES) * SB;
        const size_t go = (size_t)c * 32 + seg * 4;
#pragma unroll
        for (int i = 0; i < 4; i++) {
            const int r = row0 + i * 32;
            const uint32_t sw = swz(r, seg * 4);
            CPA16(base + sw,        Ah + (m0 + r) * 512 + go);
            CPA16(base + TILE + sw, Bh + (n0 + r) * 512 + go);
            if (SPLIT) {
                CPA16(base + 2 * TILE + sw, Al + (m0 + r) * 512 + go);
                CPA16(base + 3 * TILE + sw, Bl + (n0 + r) * 512 + go);
            }
        }
    };

    float acc[2][8][4] = {};

    // prologue: stages 0..STAGES-2
#pragma unroll
    for (int c = 0; c < STAGES - 1; c++) { load_chunk(c); CPA_COMMIT(); }

    for (int c = 0; c < 16; c++) {
        CPA_WAIT(STAGES - 2);
        __syncthreads();
        if (c + STAGES - 1 < 16) load_chunk(c + STAGES - 1);
        CPA_COMMIT();

        const uint32_t sA = s0 + (uint32_t)(c % STAGES) * SB;
        const uint32_t sBm = sA + TILE;

#pragma unroll
        for (int ks = 0; ks < 4; ks++) {
            const int kc = ks * 8 + tig;
            uint32_t ah[2][4];
#pragma unroll
            for (int mt = 0; mt < 2; mt++) {
                const int r = wm + mt * 16 + gid;
                ah[mt][0] = lds32(sA + swz(r,     kc));
                ah[mt][1] = lds32(sA + swz(r + 8, kc));
                ah[mt][2] = lds32(sA + swz(r,     kc + 4));
                ah[mt][3] = lds32(sA + swz(r + 8, kc + 4));
            }
            if (!SPLIT) {
#pragma unroll
                for (int nt = 0; nt < 8; nt++) {
                    const int rn = wn + nt * 8 + gid;
                    const uint32_t b0 = lds32(sBm + swz(rn, kc));
                    const uint32_t b1 = lds32(sBm + swz(rn, kc + 4));
                    MMA_TF32(acc[0][nt], ah[0], b0, b1);
                    MMA_TF32(acc[1][nt], ah[1], b0, b1);
                }
            } else {
                const uint32_t sAl = sA + 2 * TILE, sBl = sA + 3 * TILE;
                uint32_t al[2][4];
#pragma unroll
                for (int mt = 0; mt < 2; mt++) {
                    const int r = wm + mt * 16 + gid;
                    al[mt][0] = lds32(sAl + swz(r,     kc));
                    al[mt][1] = lds32(sAl + swz(r + 8, kc));
                    al[mt][2] = lds32(sAl + swz(r,     kc + 4));
                    al[mt][3] = lds32(sAl + swz(r + 8, kc + 4));
                }
#pragma unroll
                for (int nt = 0; nt < 8; nt++) {
                    const int rn = wn + nt * 8 + gid;
                    const uint32_t bh0 = lds32(sBm + swz(rn, kc));
                    const uint32_t bh1 = lds32(sBm + swz(rn, kc + 4));
                    MMA_TF32(acc[0][nt], ah[0], bh0, bh1);
                    MMA_TF32(acc[1][nt], ah[1], bh0, bh1);
                    MMA_TF32(acc[0][nt], al[0], bh0, bh1);
                    MMA_TF32(acc[1][nt], al[1], bh0, bh1);
                    const uint32_t bl0 = lds32(sBl + swz(rn, kc));
                    const uint32_t bl1 = lds32(sBl + swz(rn, kc + 4));
                    MMA_TF32(acc[0][nt], ah[0], bl0, bl1);
                    MMA_TF32(acc[1][nt], ah[1], bl0, bl1);
                }
            }
        }
    }

    // epilogue: c0,c1 -> (row=gid, col=2*tig, 2*tig+1); c2,c3 -> row=gid+8
#pragma unroll
    for (int mt = 0; mt < 2; mt++) {
        const size_t r0 = m0 + wm + mt * 16 + gid;
#pragma unroll
        for (int nt = 0; nt < 8; nt++) {
            const size_t cc = n0 + wn + nt * 8 + tig * 2;
            *(float2*)(C + r0 * 512 + cc)       = make_float2(acc[mt][nt][0], acc[mt][nt][1]);
            *(float2*)(C + (r0 + 8) * 512 + cc) = make_float2(acc[mt][nt][2], acc[mt][nt][3]);
        }
    }
}

// ---------------------------------------------------------------------------
// Row softmax over g_attn; output tf32-rounded for GEMM2.
// ---------------------------------------------------------------------------
__global__ void softmax_kernel()
{
    const int row = blockIdx.x;
    const int tid = threadIdx.x;
    float* rp = g_attn + (size_t)row * 512;

    float4 v = *(float4*)(rp + tid * 4);
    float m = fmaxf(fmaxf(v.x, v.y), fmaxf(v.z, v.w));
#pragma unroll
    for (int o = 16; o > 0; o >>= 1) m = fmaxf(m, __shfl_xor_sync(0xFFFFFFFFu, m, o));

    __shared__ float sred[4];
    const int wid = tid >> 5, lane = tid & 31;
    if (lane == 0) sred[wid] = m;
    __syncthreads();
    m = fmaxf(fmaxf(sred[0], sred[1]), fmaxf(sred[2], sred[3]));
    __syncthreads();

    v.x = __expf(v.x - m); v.y = __expf(v.y - m);
    v.z = __expf(v.z - m); v.w = __expf(v.w - m);
    float s = v.x + v.y + v.z + v.w;
#pragma unroll
    for (int o = 16; o > 0; o >>= 1) s += __shfl_xor_sync(0xFFFFFFFFu, s, o);
    if (lane == 0) sred[wid] = s;
    __syncthreads();
    s = sred[0] + sred[1] + sred[2] + sred[3];

    const float inv = 1.0f / s;
    v.x = tf32r(v.x * inv); v.y = tf32r(v.y * inv);
    v.z = tf32r(v.z * inv); v.w = tf32r(v.w * inv);
    *(float4*)(rp + tid * 4) = v;
}

// ---------------------------------------------------------------------------
extern "C" void kernel_launch(void* const* d_in, const int* in_sizes, int n_in,
                              void* d_out, int out_size)
{
    const float* x  = (const float*)d_in[0];
    const float* Wq = (const float*)d_in[1];
    const float* bq = (const float*)d_in[2];
    const float* Wk = (const float*)d_in[3];
    const float* bk = (const float*)d_in[4];
    const float* Wv = (const float*)d_in[5];
    const float* bv = (const float*)d_in[6];
    float* out = (float*)d_out;

    float *pqh, *pql, *pkh, *pkl, *pvT, *pattn;
    cudaGetSymbolAddress((void**)&pqh,  g_qhi);
    cudaGetSymbolAddress((void**)&pql,  g_qlo);
    cudaGetSymbolAddress((void**)&pkh,  g_khi);
    cudaGetSymbolAddress((void**)&pkl,  g_klo);
    cudaGetSymbolAddress((void**)&pvT,  g_vT);
    cudaGetSymbolAddress((void**)&pattn, g_attn);

    const int SMEM_S = 3 * 4 * 16384;   // 192 KB (split)
    const int SMEM_N = 3 * 2 * 16384;   // 96 KB
    cudaFuncSetAttribute(gemm_mma<true>,  cudaFuncAttributeMaxDynamicSharedMemorySize, SMEM_S);
    cudaFuncSetAttribute(gemm_mma<false>, cudaFuncAttributeMaxDynamicSharedMemorySize, SMEM_N);

    // 1) q,k (tf32 hi/lo), vT (tf32)
    qkv_kernel<<<dim3(16, 16, BATCH), 256>>>(x, Wq, bq, Wk, bk, Wv, bv);

    // 2) logits = q k^T per batch (3xTF32)
    gemm_mma<true><<<dim3(4, 4, BATCH), 256, SMEM_S>>>(pqh, pql, pkh, pkl, pattn, 0);

    // 3) softmax rows (+ tf32 rounding)
    softmax_kernel<<<BATCH * 512, 128>>>();

    // 4) out = attn @ vT per (b,c), single tf32
    gemm_mma<false><<<dim3(4, 4, BATCH * 8), 256, SMEM_N>>>(pattn, pattn, pvT, pvT, out, 3);
}